// round 5
// baseline (speedup 1.0000x reference)
#include <cuda_runtime.h>
#include <math.h>

// Problem dims
#define L_ 16
#define H_ 8
#define D_ 768
#define DH_ 96
#define F_ 2048
#define V_ 32000
#define B_ 2
#define S_ 1024
#define BS_ (B_ * S_)
#define EPS_ 1e-6f
#define PIPE 3

// Activation scratch (padded so unpredicated tile loads stay in-bounds)
__device__ float g_x[BS_ * D_ + 256];
__device__ float g_xn[BS_ * D_ + 256];
__device__ float g_q[BS_ * D_ + 256];
__device__ float g_k[BS_ * D_ + 256];
__device__ float g_v[BS_ * D_ + 256];
__device__ float g_o[BS_ * D_ + 256];
__device__ float g_att[(long long)B_ * H_ * S_ * S_ + 256];
__device__ float g_ffn[BS_ * F_ + 256];

// TF32-rounded weight copies
__device__ float g_cwq[L_ * D_ * D_];
__device__ float g_cwk[L_ * D_ * D_];
__device__ float g_cwv[L_ * D_ * D_];
__device__ float g_cwo[L_ * D_ * D_];
__device__ float g_cw1[(long long)L_ * D_ * F_];
__device__ float g_cw2[(long long)L_ * F_ * D_];
__device__ float g_cow[(long long)D_ * V_];

struct MultiPtr {
    const float* B[3];
    float* C[3];
};

__device__ __forceinline__ unsigned f2tf32(float x) {
    unsigned r;
    asm("cvt.rna.tf32.f32 %0, %1;" : "=r"(r) : "f"(x));
    return r;
}
__device__ __forceinline__ float roundtf(float x) { return __uint_as_float(f2tf32(x)); }

// ---------------------------------------------------------------------------
// Weight -> TF32 rounding
// ---------------------------------------------------------------------------
__global__ void cvt_tf32_kernel(const float4* __restrict__ in, float4* __restrict__ out,
                                long long n4) {
    long long i = (long long)blockIdx.x * blockDim.x + threadIdx.x;
    long long stride = (long long)gridDim.x * blockDim.x;
    for (; i < n4; i += stride) {
        float4 v = in[i];
        v.x = roundtf(v.x); v.y = roundtf(v.y); v.z = roundtf(v.z); v.w = roundtf(v.w);
        out[i] = v;
    }
}

// ---------------------------------------------------------------------------
// Fused embedding + RMSNorm (residual stream: full fp32)
// ---------------------------------------------------------------------------
__global__ void embed_norm_kernel(const int* __restrict__ tok,
                                  const float* __restrict__ tok_emb,
                                  const float* __restrict__ pos_emb,
                                  const float* __restrict__ w) {
    int row = blockIdx.x;
    int s = row % S_;
    int t = tok[row];
    __shared__ float buf[D_];
    __shared__ float red[256];
    float ss = 0.f;
    for (int d = threadIdx.x; d < D_; d += 256) {
        float v = tok_emb[(long long)t * D_ + d] + pos_emb[(long long)s * D_ + d];
        buf[d] = v;
        ss += v * v;
    }
    red[threadIdx.x] = ss;
    __syncthreads();
    for (int o = 128; o > 0; o >>= 1) {
        if (threadIdx.x < o) red[threadIdx.x] += red[threadIdx.x + o];
        __syncthreads();
    }
    float inv = rsqrtf(red[0] / (float)D_ + EPS_);
    for (int d = threadIdx.x; d < D_; d += 256)
        g_x[(long long)row * D_ + d] = buf[d] * inv * w[d];
}

// ---------------------------------------------------------------------------
// RMSNorm; output rounded to tf32
// ---------------------------------------------------------------------------
__global__ void rmsnorm_kernel(const float* __restrict__ in, float* __restrict__ out,
                               const float* __restrict__ w, int n) {
    long long row = blockIdx.x;
    const float* x = in + row * n;
    float ss = 0.f;
    for (int d = threadIdx.x; d < n; d += 256) { float v = x[d]; ss += v * v; }
    __shared__ float red[256];
    red[threadIdx.x] = ss;
    __syncthreads();
    for (int o = 128; o > 0; o >>= 1) {
        if (threadIdx.x < o) red[threadIdx.x] += red[threadIdx.x + o];
        __syncthreads();
    }
    float inv = rsqrtf(red[0] / (float)n + EPS_);
    float* y = out + row * n;
    for (int d = threadIdx.x; d < n; d += 256) y[d] = roundtf(x[d] * inv * w[d]);
}

// ---------------------------------------------------------------------------
// TF32 tensor-core GEMM, cp.async 3-stage pipeline.
// mode: 0 = normal (x=n, y=m); 1 = swapped (x=m, y=n); 2 = triangular (x=pair)
// kcap: if nonzero, K = min(K, m0 + BM)  (causal PV)
// ---------------------------------------------------------------------------
__device__ __forceinline__ void cp16(float* dst, const float* src) {
    unsigned d = (unsigned)__cvta_generic_to_shared(dst);
    asm volatile("cp.async.cg.shared.global [%0], [%1], 16;" :: "r"(d), "l"(src));
}

__device__ __forceinline__ void mma_tf32(float* d, const unsigned* a, const unsigned* b) {
    asm volatile("mma.sync.aligned.m16n8k8.row.col.f32.tf32.tf32.f32 "
                 "{%0,%1,%2,%3}, {%4,%5,%6,%7}, {%8,%9}, {%0,%1,%2,%3};"
                 : "+f"(d[0]), "+f"(d[1]), "+f"(d[2]), "+f"(d[3])
                 : "r"(a[0]), "r"(a[1]), "r"(a[2]), "r"(a[3]),
                   "r"(b[0]), "r"(b[1]));
}

__device__ __forceinline__ float gelu_tanh(float x) {
    return 0.5f * x * (1.f + tanhf(0.7978845608028654f * (x + 0.044715f * x * x * x)));
}

#define BFL 4608  // floats for B tile per stage (max of 128*36, 32*132)

template <bool TRANSB, int BM>
__global__ void __launch_bounds__(256) gemm_tc_async(
    const float* __restrict__ A, int lda, long long saO, long long saI,
    const float* __restrict__ Bp, int ldb, long long sbO, long long sbI,
    float* __restrict__ C, int ldc, long long scO, long long scI,
    const float* __restrict__ R,
    int M, int N, int K, float alpha, int gelu_flag, int round_flag,
    int mode, int kcap, int hdiv, MultiPtr P, int nmulti)
{
    constexpr int WM = BM / 32;
    constexpr int WN = 8 / WM;
    constexpr int WTN = 128 / WN;
    constexpr int NT = WTN / 8;
    constexpr int STAGE = BM * 36 + BFL;

    extern __shared__ float smf[];

    int z = blockIdx.z;
    if (nmulti > 1) {
        Bp = P.B[z];
        C = P.C[z];
    } else {
        int zo = z / hdiv, zi = z % hdiv;
        A  += (long long)zo * saO + (long long)zi * saI;
        Bp += (long long)zo * sbO + (long long)zi * sbI;
        long long co = (long long)zo * scO + (long long)zi * scI;
        C += co;
        if (R) R += co;
    }

    int m0, n0;
    if (mode == 2) {  // triangular lower: enumerate pairs (bm, bn), bn <= bm
        int p = blockIdx.x;
        int bm = (int)((sqrtf(8.f * p + 1.f) - 1.f) * 0.5f);
        while ((bm + 1) * (bm + 2) / 2 <= p) bm++;
        while (bm * (bm + 1) / 2 > p) bm--;
        int bn = p - bm * (bm + 1) / 2;
        m0 = bm * BM; n0 = bn * 128;
    } else if (mode == 1) {
        m0 = blockIdx.x * BM; n0 = blockIdx.y * 128;
    } else {
        m0 = blockIdx.y * BM; n0 = blockIdx.x * 128;
    }
    if (kcap) K = min(K, m0 + BM);

    int tid = threadIdx.x;
    int warp = tid >> 5, lane = tid & 31;
    int g = lane >> 2, t = lane & 3;
    int mwarp = (warp % WM) * 32;
    int nwarp = (warp / WM) * WTN;

    float acc[2][NT][4];
    #pragma unroll
    for (int i = 0; i < 2; i++)
        #pragma unroll
        for (int j = 0; j < NT; j++)
            #pragma unroll
            for (int r = 0; r < 4; r++) acc[i][j][r] = 0.f;

    const int KT = K >> 5;

    auto stage = [&](int kt, int sbuf) {
        float* Asf = smf + sbuf * STAGE;
        float* Bsf = Asf + BM * 36;
        int k0 = kt * 32;
        #pragma unroll
        for (int i = 0; i < BM / 32; i++) {
            int f = tid + i * 256;
            int row = f >> 3, ch = f & 7;
            cp16(Asf + row * 36 + ch * 4,
                 A + (long long)(m0 + row) * lda + k0 + ch * 4);
        }
        if (TRANSB) {
            #pragma unroll
            for (int i = 0; i < 4; i++) {
                int f = tid + i * 256;
                int row = f >> 3, ch = f & 7;
                cp16(Bsf + row * 36 + ch * 4,
                     Bp + (long long)(n0 + row) * ldb + k0 + ch * 4);
            }
        } else {
            #pragma unroll
            for (int i = 0; i < 4; i++) {
                int f = tid + i * 256;
                int kk = f >> 5, ch = f & 31;
                cp16(Bsf + kk * 132 + ch * 4,
                     Bp + (long long)(k0 + kk) * ldb + n0 + ch * 4);
            }
        }
        asm volatile("cp.async.commit_group;" ::: "memory");
    };

    for (int s = 0; s < PIPE - 1 && s < KT; s++) stage(s, s);

    for (int kt = 0; kt < KT; kt++) {
        if (kt == KT - 1) asm volatile("cp.async.wait_group 0;" ::: "memory");
        else              asm volatile("cp.async.wait_group %0;" :: "n"(PIPE - 2) : "memory");
        __syncthreads();

        int nk = kt + PIPE - 1;
        if (nk < KT) stage(nk, nk % PIPE);

        const unsigned* Asu = (const unsigned*)(smf + (kt % PIPE) * STAGE);
        const unsigned* Bsu = Asu + BM * 36;

        #pragma unroll
        for (int ks = 0; ks < 4; ks++) {
            int krow = ks * 8 + t;
            unsigned af[2][4];
            #pragma unroll
            for (int mt = 0; mt < 2; mt++) {
                int m = mwarp + mt * 16 + g;
                af[mt][0] = Asu[m * 36 + krow];
                af[mt][1] = Asu[(m + 8) * 36 + krow];
                af[mt][2] = Asu[m * 36 + krow + 4];
                af[mt][3] = Asu[(m + 8) * 36 + krow + 4];
            }
            unsigned bf[NT][2];
            #pragma unroll
            for (int nt = 0; nt < NT; nt++) {
                int n = nwarp + nt * 8 + g;
                if (TRANSB) {
                    bf[nt][0] = Bsu[n * 36 + krow];
                    bf[nt][1] = Bsu[n * 36 + krow + 4];
                } else {
                    bf[nt][0] = Bsu[krow * 132 + n];
                    bf[nt][1] = Bsu[(krow + 4) * 132 + n];
                }
            }
            #pragma unroll
            for (int mt = 0; mt < 2; mt++)
                #pragma unroll
                for (int nt = 0; nt < NT; nt++)
                    mma_tf32(acc[mt][nt], af[mt], bf[nt]);
        }
        __syncthreads();
    }

    // --- Epilogue
    #pragma unroll
    for (int mt = 0; mt < 2; mt++) {
        #pragma unroll
        for (int nt = 0; nt < NT; nt++) {
            #pragma unroll
            for (int r = 0; r < 4; r++) {
                int row = m0 + mwarp + mt * 16 + g + ((r & 2) ? 8 : 0);
                int col = n0 + nwarp + nt * 8 + t * 2 + (r & 1);
                if (row < M && col < N) {
                    float v = acc[mt][nt][r] * alpha;
                    if (R) v += R[(long long)row * ldc + col];
                    if (gelu_flag) v = gelu_tanh(v);
                    if (round_flag) v = roundtf(v);
                    C[(long long)row * ldc + col] = v;
                }
            }
        }
    }
}

// ---------------------------------------------------------------------------
// Single-pass causal softmax: row cached in registers (S=1024 = 256 thr x 4).
// Writes probs (tf32-rounded) for j<=i, zeros up to next 128 boundary.
// ---------------------------------------------------------------------------
__global__ void __launch_bounds__(256) softmax_causal_kernel(float* __restrict__ att) {
    long long idx = blockIdx.x;
    int i = (int)(idx % S_);
    float4* row = (float4*)(att + idx * S_);
    int n = i + 1;
    int fill = min(S_, (n + 127) & ~127);

    int tid = threadIdx.x;
    int j0 = tid * 4;
    float v0 = -INFINITY, v1 = -INFINITY, v2 = -INFINITY, v3 = -INFINITY;
    if (j0 < n) {
        float4 r = row[tid];
        v0 = r.x;
        v1 = (j0 + 1 < n) ? r.y : -INFINITY;
        v2 = (j0 + 2 < n) ? r.z : -INFINITY;
        v3 = (j0 + 3 < n) ? r.w : -INFINITY;
    }

    __shared__ float red[8];
    // --- max
    float mx = fmaxf(fmaxf(v0, v1), fmaxf(v2, v3));
    #pragma unroll
    for (int o = 16; o > 0; o >>= 1) mx = fmaxf(mx, __shfl_xor_sync(~0u, mx, o));
    if ((tid & 31) == 0) red[tid >> 5] = mx;
    __syncthreads();
    mx = red[0];
    #pragma unroll
    for (int w = 1; w < 8; w++) mx = fmaxf(mx, red[w]);
    __syncthreads();

    // --- exp + sum (exp(-inf - mx) = 0 handles masked lanes)
    float e0 = __expf(v0 - mx), e1 = __expf(v1 - mx);
    float e2 = __expf(v2 - mx), e3 = __expf(v3 - mx);
    float sum = (e0 + e1) + (e2 + e3);
    #pragma unroll
    for (int o = 16; o > 0; o >>= 1) sum += __shfl_xor_sync(~0u, sum, o);
    if ((tid & 31) == 0) red[tid >> 5] = sum;
    __syncthreads();
    sum = red[0];
    #pragma unroll
    for (int w = 1; w < 8; w++) sum += red[w];
    float inv = 1.f / sum;

    if (j0 < fill) {
        float4 w;
        w.x = roundtf(e0 * inv);
        w.y = roundtf(e1 * inv);
        w.z = roundtf(e2 * inv);
        w.w = roundtf(e3 * inv);
        row[tid] = w;
    }
}

// ---------------------------------------------------------------------------
// Host launch helpers
// ---------------------------------------------------------------------------
template <bool TB, int BM>
static void run_gemm(dim3 grid,
                     const float* A, int lda, long long saO, long long saI,
                     const float* Bp, int ldb, long long sbO, long long sbI,
                     float* C, int ldc, long long scO, long long scI,
                     const float* R, int M, int N, int K,
                     float alpha, int gelu_flag, int round_flag,
                     int mode, int kcap, int hdiv, MultiPtr mp, int nmulti)
{
    size_t smem = (size_t)PIPE * (BM * 36 + BFL) * sizeof(float);
    cudaFuncSetAttribute(gemm_tc_async<TB, BM>,
                         cudaFuncAttributeMaxDynamicSharedMemorySize, (int)smem);
    gemm_tc_async<TB, BM><<<grid, 256, smem>>>(A, lda, saO, saI, Bp, ldb, sbO, sbI,
                                               C, ldc, scO, scI, R, M, N, K,
                                               alpha, gelu_flag, round_flag,
                                               mode, kcap, hdiv, mp, nmulti);
}

static void cvt_weights(const float* src, float* dst, long long n) {
    cvt_tf32_kernel<<<1184, 256>>>((const float4*)src, (float4*)dst, n >> 2);
}

extern "C" void kernel_launch(void* const* d_in, const int* in_sizes, int n_in,
                              void* d_out, int out_size) {
    const int*   tok         = (const int*)d_in[0];
    const float* tok_emb     = (const float*)d_in[1];
    const float* pos_emb     = (const float*)d_in[2];
    const float* pos_norm_w  = (const float*)d_in[3];
    const float* attn_norm_w = (const float*)d_in[4];
    const float* wq          = (const float*)d_in[5];
    const float* wk          = (const float*)d_in[6];
    const float* wv          = (const float*)d_in[7];
    const float* wo          = (const float*)d_in[8];
    const float* ffn_norm_w  = (const float*)d_in[9];
    const float* w1          = (const float*)d_in[10];
    const float* w2          = (const float*)d_in[11];
    const float* out_norm_w  = (const float*)d_in[12];
    const float* out_w       = (const float*)d_in[13];
    float* out = (float*)d_out;

    float *x, *xn, *q, *k, *v, *o, *att, *ffn;
    float *cwq, *cwk, *cwv, *cwo, *cw1, *cw2, *cow;
    cudaGetSymbolAddress((void**)&x,   g_x);
    cudaGetSymbolAddress((void**)&xn,  g_xn);
    cudaGetSymbolAddress((void**)&q,   g_q);
    cudaGetSymbolAddress((void**)&k,   g_k);
    cudaGetSymbolAddress((void**)&v,   g_v);
    cudaGetSymbolAddress((void**)&o,   g_o);
    cudaGetSymbolAddress((void**)&att, g_att);
    cudaGetSymbolAddress((void**)&ffn, g_ffn);
    cudaGetSymbolAddress((void**)&cwq, g_cwq);
    cudaGetSymbolAddress((void**)&cwk, g_cwk);
    cudaGetSymbolAddress((void**)&cwv, g_cwv);
    cudaGetSymbolAddress((void**)&cwo, g_cwo);
    cudaGetSymbolAddress((void**)&cw1, g_cw1);
    cudaGetSymbolAddress((void**)&cw2, g_cw2);
    cudaGetSymbolAddress((void**)&cow, g_cow);

    const float scale = 0.102062072615966f;  // 1/sqrt(96)
    const long long SS = (long long)S_ * S_;
    MultiPtr mp0 = {};

    // Pre-round weights to tf32
    cvt_weights(wq, cwq, (long long)L_ * D_ * D_);
    cvt_weights(wk, cwk, (long long)L_ * D_ * D_);
    cvt_weights(wv, cwv, (long long)L_ * D_ * D_);
    cvt_weights(wo, cwo, (long long)L_ * D_ * D_);
    cvt_weights(w1, cw1, (long long)L_ * D_ * F_);
    cvt_weights(w2, cw2, (long long)L_ * F_ * D_);
    cvt_weights(out_w, cow, (long long)D_ * V_);

    embed_norm_kernel<<<BS_, 256>>>(tok, tok_emb, pos_emb, pos_norm_w);

    for (int l = 0; l < L_; l++) {
        const float* lwq = cwq + (long long)l * D_ * D_;
        const float* lwk = cwk + (long long)l * D_ * D_;
        const float* lwv = cwv + (long long)l * D_ * D_;
        const float* lwo = cwo + (long long)l * D_ * D_;
        const float* lw1 = cw1 + (long long)l * D_ * F_;
        const float* lw2 = cw2 + (long long)l * F_ * D_;

        rmsnorm_kernel<<<BS_, 256>>>(x, xn, attn_norm_w + (long long)l * D_, D_);

        // fused QKV (outputs rounded)
        MultiPtr mq;
        mq.B[0] = lwq; mq.B[1] = lwk; mq.B[2] = lwv;
        mq.C[0] = q;   mq.C[1] = k;   mq.C[2] = v;
        run_gemm<false, 128>(dim3(6, 16, 3),
                             xn, D_, 0, 0, lwq, D_, 0, 0, q, D_, 0, 0,
                             nullptr, BS_, D_, D_, 1.f, 0, 1, 0, 0, 1, mq, 3);

        // scores: lower-triangular block tiles only (36 pairs x 16 heads)
        run_gemm<true, 128>(dim3(36, 1, 16),
                            q, D_, (long long)S_ * D_, DH_,
                            k, D_, (long long)S_ * D_, DH_,
                            att, S_, (long long)H_ * SS, SS,
                            nullptr, S_, S_, DH_, scale, 0, 0, 2, 0, H_, mp0, 1);

        softmax_causal_kernel<<<B_ * H_ * S_, 256>>>(att);

        // o = probs @ V_h, K capped at m0+64 (causal)
        run_gemm<false, 64>(dim3(1, 16, 16),
                            att, S_, (long long)H_ * SS, SS,
                            v, D_, (long long)S_ * D_, DH_,
                            o, D_, (long long)S_ * D_, DH_,
                            nullptr, S_, DH_, S_, 1.f, 0, 1, 0, 1, H_, mp0, 1);

        // x = x + o @ wo
        run_gemm<false, 64>(dim3(6, 32, 1),
                            o, D_, 0, 0, lwo, D_, 0, 0, x, D_, 0, 0,
                            x, BS_, D_, D_, 1.f, 0, 0, 0, 0, 1, mp0, 1);

        rmsnorm_kernel<<<BS_, 256>>>(x, xn, ffn_norm_w + (long long)l * D_, D_);

        // ffn = round(gelu(xn @ w1))
        run_gemm<false, 128>(dim3(16, 16, 1),
                             xn, D_, 0, 0, lw1, F_, 0, 0, ffn, F_, 0, 0,
                             nullptr, BS_, F_, D_, 1.f, 1, 1, 0, 0, 1, mp0, 1);

        // x = x + ffn @ w2
        run_gemm<false, 64>(dim3(6, 32, 1),
                            ffn, F_, 0, 0, lw2, D_, 0, 0, x, D_, 0, 0,
                            x, BS_, D_, F_, 1.f, 0, 0, 0, 0, 1, mp0, 1);
    }

    rmsnorm_kernel<<<BS_, 256>>>(x, xn, out_norm_w, D_);
    // logits: swapped raster (m fastest) so concurrent CTAs share out_w tiles in L2
    run_gemm<false, 128>(dim3(16, 250, 1),
                         xn, D_, 0, 0, cow, V_, 0, 0, out, V_, 0, 0,
                         nullptr, BS_, V_, D_, 1.f, 0, 0, 1, 0, 1, mp0, 1);
}

// round 6
// speedup vs baseline: 1.5049x; 1.5049x over previous
#include <cuda_runtime.h>
#include <math.h>

// Problem dims
#define L_ 16
#define H_ 8
#define D_ 768
#define DH_ 96
#define F_ 2048
#define V_ 32000
#define B_ 2
#define S_ 1024
#define BS_ (B_ * S_)
#define EPS_ 1e-6f
#define PIPE 3

// Activation scratch (padded so unpredicated tile loads stay in-bounds)
__device__ float g_x[BS_ * D_ + 256];
__device__ float g_xn[BS_ * D_ + 256];
__device__ float g_q[BS_ * D_ + 256];
__device__ float g_k[BS_ * D_ + 256];
__device__ float g_v[BS_ * D_ + 256];
__device__ float g_o[BS_ * D_ + 256];
__device__ float g_att[(long long)B_ * H_ * S_ * S_ + 256];
__device__ float g_ffn[BS_ * F_ + 256];

// TF32-rounded weight copies
__device__ float g_cwq[L_ * D_ * D_];
__device__ float g_cwk[L_ * D_ * D_];
__device__ float g_cwv[L_ * D_ * D_];
__device__ float g_cwo[L_ * D_ * D_];
__device__ float g_cw1[(long long)L_ * D_ * F_];
__device__ float g_cw2[(long long)L_ * F_ * D_];
__device__ float g_cow[(long long)D_ * V_];

struct MultiPtr {
    const float* B[3];
    float* C[3];
};

__device__ __forceinline__ unsigned f2tf32(float x) {
    unsigned r;
    asm("cvt.rna.tf32.f32 %0, %1;" : "=r"(r) : "f"(x));
    return r;
}
__device__ __forceinline__ float roundtf(float x) { return __uint_as_float(f2tf32(x)); }

// ---------------------------------------------------------------------------
// Weight -> TF32 rounding
// ---------------------------------------------------------------------------
__global__ void cvt_tf32_kernel(const float4* __restrict__ in, float4* __restrict__ out,
                                long long n4) {
    long long i = (long long)blockIdx.x * blockDim.x + threadIdx.x;
    long long stride = (long long)gridDim.x * blockDim.x;
    for (; i < n4; i += stride) {
        float4 v = in[i];
        v.x = roundtf(v.x); v.y = roundtf(v.y); v.z = roundtf(v.z); v.w = roundtf(v.w);
        out[i] = v;
    }
}

// ---------------------------------------------------------------------------
// Fused embedding + RMSNorm (residual stream: full fp32)
// ---------------------------------------------------------------------------
__global__ void embed_norm_kernel(const int* __restrict__ tok,
                                  const float* __restrict__ tok_emb,
                                  const float* __restrict__ pos_emb,
                                  const float* __restrict__ w) {
    int row = blockIdx.x;
    int s = row % S_;
    int t = tok[row];
    __shared__ float buf[D_];
    __shared__ float red[256];
    float ss = 0.f;
    for (int d = threadIdx.x; d < D_; d += 256) {
        float v = tok_emb[(long long)t * D_ + d] + pos_emb[(long long)s * D_ + d];
        buf[d] = v;
        ss += v * v;
    }
    red[threadIdx.x] = ss;
    __syncthreads();
    for (int o = 128; o > 0; o >>= 1) {
        if (threadIdx.x < o) red[threadIdx.x] += red[threadIdx.x + o];
        __syncthreads();
    }
    float inv = rsqrtf(red[0] / (float)D_ + EPS_);
    for (int d = threadIdx.x; d < D_; d += 256)
        g_x[(long long)row * D_ + d] = buf[d] * inv * w[d];
}

// ---------------------------------------------------------------------------
// RMSNorm; output rounded to tf32
// ---------------------------------------------------------------------------
__global__ void rmsnorm_kernel(const float* __restrict__ in, float* __restrict__ out,
                               const float* __restrict__ w, int n) {
    long long row = blockIdx.x;
    const float* x = in + row * n;
    float ss = 0.f;
    for (int d = threadIdx.x; d < n; d += 256) { float v = x[d]; ss += v * v; }
    __shared__ float red[256];
    red[threadIdx.x] = ss;
    __syncthreads();
    for (int o = 128; o > 0; o >>= 1) {
        if (threadIdx.x < o) red[threadIdx.x] += red[threadIdx.x + o];
        __syncthreads();
    }
    float inv = rsqrtf(red[0] / (float)n + EPS_);
    float* y = out + row * n;
    for (int d = threadIdx.x; d < n; d += 256) y[d] = roundtf(x[d] * inv * w[d]);
}

// ---------------------------------------------------------------------------
// TF32 tensor-core GEMM, cp.async 3-stage pipeline.
// mode: 0 = normal (x=n, y=m); 1 = swapped (x=m, y=n); 2 = triangular (x=pair)
// kcap: if nonzero, K = min(K, m0 + BM)  (causal PV)
// __launch_bounds__(256, 2): force regs <= 128 so 2 CTAs/SM always fit.
// ---------------------------------------------------------------------------
__device__ __forceinline__ void cp16(float* dst, const float* src) {
    unsigned d = (unsigned)__cvta_generic_to_shared(dst);
    asm volatile("cp.async.cg.shared.global [%0], [%1], 16;" :: "r"(d), "l"(src));
}

__device__ __forceinline__ void mma_tf32(float* d, const unsigned* a, const unsigned* b) {
    asm volatile("mma.sync.aligned.m16n8k8.row.col.f32.tf32.tf32.f32 "
                 "{%0,%1,%2,%3}, {%4,%5,%6,%7}, {%8,%9}, {%0,%1,%2,%3};"
                 : "+f"(d[0]), "+f"(d[1]), "+f"(d[2]), "+f"(d[3])
                 : "r"(a[0]), "r"(a[1]), "r"(a[2]), "r"(a[3]),
                   "r"(b[0]), "r"(b[1]));
}

__device__ __forceinline__ float gelu_tanh(float x) {
    return 0.5f * x * (1.f + tanhf(0.7978845608028654f * (x + 0.044715f * x * x * x)));
}

#define BFL 4608  // floats for B tile per stage (max of 128*36, 32*132)

template <bool TRANSB, int BM>
__global__ void __launch_bounds__(256, 2) gemm_tc_async(
    const float* __restrict__ A, int lda, long long saO, long long saI,
    const float* __restrict__ Bp, int ldb, long long sbO, long long sbI,
    float* __restrict__ C, int ldc, long long scO, long long scI,
    const float* __restrict__ R,
    int M, int N, int K, float alpha, int gelu_flag, int round_flag,
    int mode, int kcap, int hdiv, MultiPtr P, int nmulti)
{
    constexpr int WM = BM / 32;
    constexpr int WN = 8 / WM;
    constexpr int WTN = 128 / WN;
    constexpr int NT = WTN / 8;
    constexpr int STAGE = BM * 36 + BFL;

    extern __shared__ float smf[];

    int z = blockIdx.z;
    if (nmulti > 1) {
        Bp = P.B[z];
        C = P.C[z];
    } else {
        int zo = z / hdiv, zi = z % hdiv;
        A  += (long long)zo * saO + (long long)zi * saI;
        Bp += (long long)zo * sbO + (long long)zi * sbI;
        long long co = (long long)zo * scO + (long long)zi * scI;
        C += co;
        if (R) R += co;
    }

    int m0, n0;
    if (mode == 2) {  // triangular lower: p -> (bm, bn), bn <= bm (integer loop)
        int p = blockIdx.x;
        int bm = 0;
        while ((bm + 1) * (bm + 2) / 2 <= p) bm++;
        int bn = p - bm * (bm + 1) / 2;
        m0 = bm * BM; n0 = bn * 128;
    } else if (mode == 1) {
        m0 = blockIdx.x * BM; n0 = blockIdx.y * 128;
    } else {
        m0 = blockIdx.y * BM; n0 = blockIdx.x * 128;
    }
    if (kcap) K = min(K, m0 + BM);

    int tid = threadIdx.x;
    int warp = tid >> 5, lane = tid & 31;
    int g = lane >> 2, t = lane & 3;
    int mwarp = (warp % WM) * 32;
    int nwarp = (warp / WM) * WTN;

    float acc[2][NT][4];
    #pragma unroll
    for (int i = 0; i < 2; i++)
        #pragma unroll
        for (int j = 0; j < NT; j++)
            #pragma unroll
            for (int r = 0; r < 4; r++) acc[i][j][r] = 0.f;

    const int KT = K >> 5;

    auto stage = [&](int kt, int sbuf) {
        float* Asf = smf + sbuf * STAGE;
        float* Bsf = Asf + BM * 36;
        int k0 = kt * 32;
        #pragma unroll
        for (int i = 0; i < BM / 32; i++) {
            int f = tid + i * 256;
            int row = f >> 3, ch = f & 7;
            cp16(Asf + row * 36 + ch * 4,
                 A + (long long)(m0 + row) * lda + k0 + ch * 4);
        }
        if (TRANSB) {
            #pragma unroll
            for (int i = 0; i < 4; i++) {
                int f = tid + i * 256;
                int row = f >> 3, ch = f & 7;
                cp16(Bsf + row * 36 + ch * 4,
                     Bp + (long long)(n0 + row) * ldb + k0 + ch * 4);
            }
        } else {
            #pragma unroll
            for (int i = 0; i < 4; i++) {
                int f = tid + i * 256;
                int kk = f >> 5, ch = f & 31;
                cp16(Bsf + kk * 132 + ch * 4,
                     Bp + (long long)(k0 + kk) * ldb + n0 + ch * 4);
            }
        }
        asm volatile("cp.async.commit_group;" ::: "memory");
    };

    for (int s = 0; s < PIPE - 1 && s < KT; s++) stage(s, s);

    for (int kt = 0; kt < KT; kt++) {
        if (kt == KT - 1) asm volatile("cp.async.wait_group 0;" ::: "memory");
        else              asm volatile("cp.async.wait_group %0;" :: "n"(PIPE - 2) : "memory");
        __syncthreads();

        int nk = kt + PIPE - 1;
        if (nk < KT) stage(nk, nk % PIPE);

        const unsigned* Asu = (const unsigned*)(smf + (kt % PIPE) * STAGE);
        const unsigned* Bsu = Asu + BM * 36;

        #pragma unroll
        for (int ks = 0; ks < 4; ks++) {
            int krow = ks * 8 + t;
            unsigned af[2][4];
            #pragma unroll
            for (int mt = 0; mt < 2; mt++) {
                int m = mwarp + mt * 16 + g;
                af[mt][0] = Asu[m * 36 + krow];
                af[mt][1] = Asu[(m + 8) * 36 + krow];
                af[mt][2] = Asu[m * 36 + krow + 4];
                af[mt][3] = Asu[(m + 8) * 36 + krow + 4];
            }
            unsigned bf[NT][2];
            #pragma unroll
            for (int nt = 0; nt < NT; nt++) {
                int n = nwarp + nt * 8 + g;
                if (TRANSB) {
                    bf[nt][0] = Bsu[n * 36 + krow];
                    bf[nt][1] = Bsu[n * 36 + krow + 4];
                } else {
                    bf[nt][0] = Bsu[krow * 132 + n];
                    bf[nt][1] = Bsu[(krow + 4) * 132 + n];
                }
            }
            #pragma unroll
            for (int mt = 0; mt < 2; mt++)
                #pragma unroll
                for (int nt = 0; nt < NT; nt++)
                    mma_tf32(acc[mt][nt], af[mt], bf[nt]);
        }
        __syncthreads();
    }

    // --- Epilogue
    #pragma unroll
    for (int mt = 0; mt < 2; mt++) {
        #pragma unroll
        for (int nt = 0; nt < NT; nt++) {
            #pragma unroll
            for (int r = 0; r < 4; r++) {
                int row = m0 + mwarp + mt * 16 + g + ((r & 2) ? 8 : 0);
                int col = n0 + nwarp + nt * 8 + t * 2 + (r & 1);
                if (row < M && col < N) {
                    float v = acc[mt][nt][r] * alpha;
                    if (R) v += R[(long long)row * ldc + col];
                    if (gelu_flag) v = gelu_tanh(v);
                    if (round_flag) v = roundtf(v);
                    C[(long long)row * ldc + col] = v;
                }
            }
        }
    }
}

// ---------------------------------------------------------------------------
// Single-pass causal softmax: row cached in registers (S=1024 = 256 thr x 4).
// Writes probs (tf32-rounded) for j<=i, zeros up to next 128 boundary.
// ---------------------------------------------------------------------------
__global__ void __launch_bounds__(256) softmax_causal_kernel(float* __restrict__ att) {
    long long idx = blockIdx.x;
    int i = (int)(idx % S_);
    float4* row = (float4*)(att + idx * S_);
    int n = i + 1;
    int fill = min(S_, (n + 127) & ~127);

    int tid = threadIdx.x;
    int j0 = tid * 4;
    float v0 = -INFINITY, v1 = -INFINITY, v2 = -INFINITY, v3 = -INFINITY;
    if (j0 < n) {
        float4 r = row[tid];
        v0 = r.x;
        v1 = (j0 + 1 < n) ? r.y : -INFINITY;
        v2 = (j0 + 2 < n) ? r.z : -INFINITY;
        v3 = (j0 + 3 < n) ? r.w : -INFINITY;
    }

    __shared__ float red[8];
    // --- max
    float mx = fmaxf(fmaxf(v0, v1), fmaxf(v2, v3));
    #pragma unroll
    for (int o = 16; o > 0; o >>= 1) mx = fmaxf(mx, __shfl_xor_sync(~0u, mx, o));
    if ((tid & 31) == 0) red[tid >> 5] = mx;
    __syncthreads();
    mx = red[0];
    #pragma unroll
    for (int w = 1; w < 8; w++) mx = fmaxf(mx, red[w]);
    __syncthreads();

    // --- exp + sum (exp(-inf - mx) = 0 handles masked lanes)
    float e0 = __expf(v0 - mx), e1 = __expf(v1 - mx);
    float e2 = __expf(v2 - mx), e3 = __expf(v3 - mx);
    float sum = (e0 + e1) + (e2 + e3);
    #pragma unroll
    for (int o = 16; o > 0; o >>= 1) sum += __shfl_xor_sync(~0u, sum, o);
    if ((tid & 31) == 0) red[tid >> 5] = sum;
    __syncthreads();
    sum = red[0];
    #pragma unroll
    for (int w = 1; w < 8; w++) sum += red[w];
    float inv = 1.f / sum;

    if (j0 < fill) {
        float4 w;
        w.x = roundtf(e0 * inv);
        w.y = roundtf(e1 * inv);
        w.z = roundtf(e2 * inv);
        w.w = roundtf(e3 * inv);
        row[tid] = w;
    }
}

// ---------------------------------------------------------------------------
// Host launch helpers
// ---------------------------------------------------------------------------
template <bool TB, int BM>
static void run_gemm(dim3 grid,
                     const float* A, int lda, long long saO, long long saI,
                     const float* Bp, int ldb, long long sbO, long long sbI,
                     float* C, int ldc, long long scO, long long scI,
                     const float* R, int M, int N, int K,
                     float alpha, int gelu_flag, int round_flag,
                     int mode, int kcap, int hdiv, MultiPtr mp, int nmulti)
{
    size_t smem = (size_t)PIPE * (BM * 36 + BFL) * sizeof(float);
    cudaFuncSetAttribute(gemm_tc_async<TB, BM>,
                         cudaFuncAttributeMaxDynamicSharedMemorySize, (int)smem);
    gemm_tc_async<TB, BM><<<grid, 256, smem>>>(A, lda, saO, saI, Bp, ldb, sbO, sbI,
                                               C, ldc, scO, scI, R, M, N, K,
                                               alpha, gelu_flag, round_flag,
                                               mode, kcap, hdiv, mp, nmulti);
}

static void cvt_weights(const float* src, float* dst, long long n) {
    cvt_tf32_kernel<<<1184, 256>>>((const float4*)src, (float4*)dst, n >> 2);
}

extern "C" void kernel_launch(void* const* d_in, const int* in_sizes, int n_in,
                              void* d_out, int out_size) {
    const int*   tok         = (const int*)d_in[0];
    const float* tok_emb     = (const float*)d_in[1];
    const float* pos_emb     = (const float*)d_in[2];
    const float* pos_norm_w  = (const float*)d_in[3];
    const float* attn_norm_w = (const float*)d_in[4];
    const float* wq          = (const float*)d_in[5];
    const float* wk          = (const float*)d_in[6];
    const float* wv          = (const float*)d_in[7];
    const float* wo          = (const float*)d_in[8];
    const float* ffn_norm_w  = (const float*)d_in[9];
    const float* w1          = (const float*)d_in[10];
    const float* w2          = (const float*)d_in[11];
    const float* out_norm_w  = (const float*)d_in[12];
    const float* out_w       = (const float*)d_in[13];
    float* out = (float*)d_out;

    float *x, *xn, *q, *k, *v, *o, *att, *ffn;
    float *cwq, *cwk, *cwv, *cwo, *cw1, *cw2, *cow;
    cudaGetSymbolAddress((void**)&x,   g_x);
    cudaGetSymbolAddress((void**)&xn,  g_xn);
    cudaGetSymbolAddress((void**)&q,   g_q);
    cudaGetSymbolAddress((void**)&k,   g_k);
    cudaGetSymbolAddress((void**)&v,   g_v);
    cudaGetSymbolAddress((void**)&o,   g_o);
    cudaGetSymbolAddress((void**)&att, g_att);
    cudaGetSymbolAddress((void**)&ffn, g_ffn);
    cudaGetSymbolAddress((void**)&cwq, g_cwq);
    cudaGetSymbolAddress((void**)&cwk, g_cwk);
    cudaGetSymbolAddress((void**)&cwv, g_cwv);
    cudaGetSymbolAddress((void**)&cwo, g_cwo);
    cudaGetSymbolAddress((void**)&cw1, g_cw1);
    cudaGetSymbolAddress((void**)&cw2, g_cw2);
    cudaGetSymbolAddress((void**)&cow, g_cow);

    const float scale = 0.102062072615966f;  // 1/sqrt(96)
    const long long SS = (long long)S_ * S_;
    MultiPtr mp0 = {};

    // Pre-round weights to tf32
    cvt_weights(wq, cwq, (long long)L_ * D_ * D_);
    cvt_weights(wk, cwk, (long long)L_ * D_ * D_);
    cvt_weights(wv, cwv, (long long)L_ * D_ * D_);
    cvt_weights(wo, cwo, (long long)L_ * D_ * D_);
    cvt_weights(w1, cw1, (long long)L_ * D_ * F_);
    cvt_weights(w2, cw2, (long long)L_ * F_ * D_);
    cvt_weights(out_w, cow, (long long)D_ * V_);

    embed_norm_kernel<<<BS_, 256>>>(tok, tok_emb, pos_emb, pos_norm_w);

    for (int l = 0; l < L_; l++) {
        const float* lwq = cwq + (long long)l * D_ * D_;
        const float* lwk = cwk + (long long)l * D_ * D_;
        const float* lwv = cwv + (long long)l * D_ * D_;
        const float* lwo = cwo + (long long)l * D_ * D_;
        const float* lw1 = cw1 + (long long)l * D_ * F_;
        const float* lw2 = cw2 + (long long)l * F_ * D_;

        rmsnorm_kernel<<<BS_, 256>>>(x, xn, attn_norm_w + (long long)l * D_, D_);

        // fused QKV (outputs rounded)
        MultiPtr mq;
        mq.B[0] = lwq; mq.B[1] = lwk; mq.B[2] = lwv;
        mq.C[0] = q;   mq.C[1] = k;   mq.C[2] = v;
        run_gemm<false, 128>(dim3(6, 16, 3),
                             xn, D_, 0, 0, lwq, D_, 0, 0, q, D_, 0, 0,
                             nullptr, BS_, D_, D_, 1.f, 0, 1, 0, 0, 1, mq, 3);

        // scores: lower-triangular block tiles only (36 pairs x 16 heads)
        run_gemm<true, 128>(dim3(36, 1, 16),
                            q, D_, (long long)S_ * D_, DH_,
                            k, D_, (long long)S_ * D_, DH_,
                            att, S_, (long long)H_ * SS, SS,
                            nullptr, S_, S_, DH_, scale, 0, 0, 2, 0, H_, mp0, 1);

        softmax_causal_kernel<<<B_ * H_ * S_, 256>>>(att);

        // o = probs @ V_h, K capped at m0+64 (causal)
        run_gemm<false, 64>(dim3(1, 16, 16),
                            att, S_, (long long)H_ * SS, SS,
                            v, D_, (long long)S_ * D_, DH_,
                            o, D_, (long long)S_ * D_, DH_,
                            nullptr, S_, DH_, S_, 1.f, 0, 1, 0, 1, H_, mp0, 1);

        // x = x + o @ wo
        run_gemm<false, 64>(dim3(6, 32, 1),
                            o, D_, 0, 0, lwo, D_, 0, 0, x, D_, 0, 0,
                            x, BS_, D_, D_, 1.f, 0, 0, 0, 0, 1, mp0, 1);

        rmsnorm_kernel<<<BS_, 256>>>(x, xn, ffn_norm_w + (long long)l * D_, D_);

        // ffn = round(gelu(xn @ w1))
        run_gemm<false, 128>(dim3(16, 16, 1),
                             xn, D_, 0, 0, lw1, F_, 0, 0, ffn, F_, 0, 0,
                             nullptr, BS_, F_, D_, 1.f, 1, 1, 0, 0, 1, mp0, 1);

        // x = x + ffn @ w2
        run_gemm<false, 64>(dim3(6, 32, 1),
                            ffn, F_, 0, 0, lw2, D_, 0, 0, x, D_, 0, 0,
                            x, BS_, D_, F_, 1.f, 0, 0, 0, 0, 1, mp0, 1);
    }

    rmsnorm_kernel<<<BS_, 256>>>(x, xn, out_norm_w, D_);
    // logits: swapped raster (m fastest) so concurrent CTAs share out_w tiles in L2
    run_gemm<false, 128>(dim3(16, 250, 1),
                         xn, D_, 0, 0, cow, V_, 0, 0, out, V_, 0, 0,
                         nullptr, BS_, V_, D_, 1.f, 0, 0, 1, 0, 1, mp0, 1);
}